// round 2
// baseline (speedup 1.0000x reference)
#include <cuda_runtime.h>
#include <math.h>

#define DM   1024
#define NH   16
#define HD   64
#define BB   4
#define TT   2048
#define MT   (BB * TT)        // 8192 rows

// Scratch (allocation rules: __device__ globals only)
__device__ float g_Q[(size_t)MT * DM];
__device__ float g_K[(size_t)MT * DM];
__device__ float g_V[(size_t)MT * DM];
__device__ float g_C[(size_t)MT * DM];

// ---------------------------------------------------------------------------
// GEMM: C[m][n] = sum_k A[m][k] * W[n][k] + bias[n]   (A: MxK row-major,
// W: NxK row-major, i.e. y = A @ W^T + b — torch Linear convention)
// MODE 0: write out[m*DM + n]           (plain (B,T,D))
// MODE 1: write head-split (B,H,T,hd):  out[((b*NH+h)*TT + t)*HD + d]
// 128x128 tile, BK=16, 256 threads, 8x8 micro-tile per thread.
// ---------------------------------------------------------------------------
template <int MODE>
__global__ __launch_bounds__(256) void gemm_kernel(
    const float* __restrict__ A, const float* __restrict__ W,
    const float* __restrict__ bias, float* __restrict__ out)
{
    __shared__ float As[16][132];
    __shared__ float Bs[16][132];

    const int tid = threadIdx.x;
    const int bm  = blockIdx.y * 128;
    const int bn  = blockIdx.x * 128;
    const int tx  = tid & 15;      // 0..15 -> N micro
    const int ty  = tid >> 4;      // 0..15 -> M micro
    const int lr  = tid >> 2;      // 0..63 loader row
    const int lk  = (tid & 3) << 2; // 0,4,8,12 loader k (float4)

    float acc[8][8];
#pragma unroll
    for (int i = 0; i < 8; i++)
#pragma unroll
        for (int j = 0; j < 8; j++) acc[i][j] = 0.f;

    for (int k0 = 0; k0 < DM; k0 += 16) {
        float4 a0 = *(const float4*)(A + (size_t)(bm + lr)      * DM + k0 + lk);
        float4 a1 = *(const float4*)(A + (size_t)(bm + lr + 64) * DM + k0 + lk);
        float4 b0 = *(const float4*)(W + (size_t)(bn + lr)      * DM + k0 + lk);
        float4 b1 = *(const float4*)(W + (size_t)(bn + lr + 64) * DM + k0 + lk);

        __syncthreads();   // previous iteration's compute done reading smem
        As[lk + 0][lr]      = a0.x; As[lk + 1][lr]      = a0.y;
        As[lk + 2][lr]      = a0.z; As[lk + 3][lr]      = a0.w;
        As[lk + 0][lr + 64] = a1.x; As[lk + 1][lr + 64] = a1.y;
        As[lk + 2][lr + 64] = a1.z; As[lk + 3][lr + 64] = a1.w;
        Bs[lk + 0][lr]      = b0.x; Bs[lk + 1][lr]      = b0.y;
        Bs[lk + 2][lr]      = b0.z; Bs[lk + 3][lr]      = b0.w;
        Bs[lk + 0][lr + 64] = b1.x; Bs[lk + 1][lr + 64] = b1.y;
        Bs[lk + 2][lr + 64] = b1.z; Bs[lk + 3][lr + 64] = b1.w;
        __syncthreads();

#pragma unroll
        for (int k = 0; k < 16; k++) {
            float a[8], b[8];
            *(float4*)(a)     = *(const float4*)&As[k][ty * 8];
            *(float4*)(a + 4) = *(const float4*)&As[k][ty * 8 + 4];
            *(float4*)(b)     = *(const float4*)&Bs[k][tx * 8];
            *(float4*)(b + 4) = *(const float4*)&Bs[k][tx * 8 + 4];
#pragma unroll
            for (int i = 0; i < 8; i++)
#pragma unroll
                for (int j = 0; j < 8; j++)
                    acc[i][j] = fmaf(a[i], b[j], acc[i][j]);
        }
    }

    // Epilogue
#pragma unroll
    for (int i = 0; i < 8; i++) {
        const int m = bm + ty * 8 + i;
        const int bidx = m / TT;
        const int t    = m % TT;
#pragma unroll
        for (int j = 0; j < 8; j++) {
            const int n = bn + tx * 8 + j;
            const float v = acc[i][j] + bias[n];
            if (MODE == 0) {
                out[(size_t)m * DM + n] = v;
            } else {
                const int h = n >> 6;
                const int d = n & 63;
                out[((size_t)(bidx * NH + h) * TT + t) * HD + d] = v;
            }
        }
    }
}

// ---------------------------------------------------------------------------
// Causal flash attention, fp32. One block = one (b,h, 64-query tile).
// 256 threads: thread owns row r = tid/4, 16 columns c = (tid&3)*16 + i.
// Online softmax; P staged through smem for the PV product.
// Writes ctx directly in (B,T,D) layout for the O projection.
// ---------------------------------------------------------------------------
#define PADW 65
#define ATT_SMEM (4 * 64 * PADW * (int)sizeof(float))   // 66560 B

__global__ __launch_bounds__(256) void attn_kernel()
{
    extern __shared__ float sm[];
    float* Qs = sm;                  // [64][65]
    float* Ks = sm + 64 * PADW;      // [64][65]
    float* Vs = sm + 2 * 64 * PADW;  // [64][65]
    float* Ps = sm + 3 * 64 * PADW;  // [64][65]

    const int tid = threadIdx.x;
    const int r   = tid >> 2;        // query row within tile (0..63)
    const int cg  = tid & 3;
    const int c0  = cg * 16;

    const int qt = blockIdx.x;       // query tile (0..31)
    const int h  = blockIdx.y;
    const int b  = blockIdx.z;
    const size_t base = (size_t)(b * NH + h) * TT * HD;
    const int q0 = qt * 64;

    // Load Q tile
#pragma unroll
    for (int u = 0; u < 4; u++) {
        float4 v = *(const float4*)(g_Q + base + (size_t)(q0 + r) * HD + c0 + u * 4);
        Qs[r * PADW + c0 + u * 4 + 0] = v.x;
        Qs[r * PADW + c0 + u * 4 + 1] = v.y;
        Qs[r * PADW + c0 + u * 4 + 2] = v.z;
        Qs[r * PADW + c0 + u * 4 + 3] = v.w;
    }

    float m_i = -1e30f, l_i = 0.f;
    float acc[16];
#pragma unroll
    for (int i = 0; i < 16; i++) acc[i] = 0.f;

    for (int j = 0; j <= qt; j++) {
        // Prefetch K/V tile to registers
        float4 kr[4], vr[4];
#pragma unroll
        for (int u = 0; u < 4; u++) {
            kr[u] = *(const float4*)(g_K + base + (size_t)(j * 64 + r) * HD + c0 + u * 4);
            vr[u] = *(const float4*)(g_V + base + (size_t)(j * 64 + r) * HD + c0 + u * 4);
        }
        __syncthreads();   // previous PV done reading Vs/Ps (and Qs ready on j==0)
#pragma unroll
        for (int u = 0; u < 4; u++) {
            Ks[r * PADW + c0 + u * 4 + 0] = kr[u].x;
            Ks[r * PADW + c0 + u * 4 + 1] = kr[u].y;
            Ks[r * PADW + c0 + u * 4 + 2] = kr[u].z;
            Ks[r * PADW + c0 + u * 4 + 3] = kr[u].w;
            Vs[r * PADW + c0 + u * 4 + 0] = vr[u].x;
            Vs[r * PADW + c0 + u * 4 + 1] = vr[u].y;
            Vs[r * PADW + c0 + u * 4 + 2] = vr[u].z;
            Vs[r * PADW + c0 + u * 4 + 3] = vr[u].w;
        }
        __syncthreads();

        // S = Q @ K^T (16 cols per thread)
        float s[16];
#pragma unroll
        for (int i = 0; i < 16; i++) s[i] = 0.f;
#pragma unroll 16
        for (int d = 0; d < 64; d++) {
            const float q = Qs[r * PADW + d];
#pragma unroll
            for (int i = 0; i < 16; i++)
                s[i] = fmaf(q, Ks[(c0 + i) * PADW + d], s[i]);
        }

        const int kbase = j * 64;
#pragma unroll
        for (int i = 0; i < 16; i++) {
            s[i] *= 0.125f;                                   // 1/sqrt(64)
            if (kbase + c0 + i > q0 + r) s[i] = -1e30f;       // causal
        }

        // Online softmax (4 threads per row cooperate via shfl)
        float mloc = s[0];
#pragma unroll
        for (int i = 1; i < 16; i++) mloc = fmaxf(mloc, s[i]);
        mloc = fmaxf(mloc, __shfl_xor_sync(0xffffffffu, mloc, 1));
        mloc = fmaxf(mloc, __shfl_xor_sync(0xffffffffu, mloc, 2));
        const float m_new = fmaxf(m_i, mloc);

        float psum = 0.f;
#pragma unroll
        for (int i = 0; i < 16; i++) {
            s[i] = __expf(s[i] - m_new);
            psum += s[i];
            Ps[r * PADW + c0 + i] = s[i];
        }
        psum += __shfl_xor_sync(0xffffffffu, psum, 1);
        psum += __shfl_xor_sync(0xffffffffu, psum, 2);

        const float corr = __expf(m_i - m_new);
        l_i = l_i * corr + psum;
        m_i = m_new;
#pragma unroll
        for (int i = 0; i < 16; i++) acc[i] *= corr;

        __syncthreads();   // Ps visible to whole row

        // O += P @ V
#pragma unroll 8
        for (int k = 0; k < 64; k++) {
            const float p = Ps[r * PADW + k];
#pragma unroll
            for (int i = 0; i < 16; i++)
                acc[i] = fmaf(p, Vs[k * PADW + c0 + i], acc[i]);
        }
    }

    // Normalize + write ctx in (B,T,D) layout
    const float inv = 1.f / l_i;
    const size_t o = ((size_t)(b * TT + q0 + r)) * DM + h * HD + c0;
#pragma unroll
    for (int u = 0; u < 4; u++) {
        float4 v = make_float4(acc[u * 4 + 0] * inv, acc[u * 4 + 1] * inv,
                               acc[u * 4 + 2] * inv, acc[u * 4 + 3] * inv);
        *(float4*)(g_C + o + u * 4) = v;
    }
}

// ---------------------------------------------------------------------------
extern "C" void kernel_launch(void* const* d_in, const int* in_sizes, int n_in,
                              void* d_out, int out_size)
{
    const float* x  = (const float*)d_in[0];
    const float* Wq = (const float*)d_in[1];
    const float* bq = (const float*)d_in[2];
    const float* Wk = (const float*)d_in[3];
    const float* bk = (const float*)d_in[4];
    const float* Wv = (const float*)d_in[5];
    const float* bv = (const float*)d_in[6];
    const float* Wo = (const float*)d_in[7];
    const float* bo = (const float*)d_in[8];
    float* out = (float*)d_out;

    float *Qp, *Kp, *Vp, *Cp;
    cudaGetSymbolAddress((void**)&Qp, g_Q);
    cudaGetSymbolAddress((void**)&Kp, g_K);
    cudaGetSymbolAddress((void**)&Vp, g_V);
    cudaGetSymbolAddress((void**)&Cp, g_C);

    cudaFuncSetAttribute(attn_kernel,
                         cudaFuncAttributeMaxDynamicSharedMemorySize, ATT_SMEM);

    dim3 ggrid(DM / 128, MT / 128);   // (8, 64)
    gemm_kernel<1><<<ggrid, 256>>>(x, Wq, bq, Qp);
    gemm_kernel<1><<<ggrid, 256>>>(x, Wk, bk, Kp);
    gemm_kernel<1><<<ggrid, 256>>>(x, Wv, bv, Vp);

    dim3 agrid(TT / 64, NH, BB);      // (32, 16, 4)
    attn_kernel<<<agrid, 256, ATT_SMEM>>>();

    gemm_kernel<0><<<ggrid, 256>>>(Cp, Wo, bo, out);
}

// round 4
// speedup vs baseline: 4.0945x; 4.0945x over previous
#include <cuda_runtime.h>
#include <math.h>
#include <stdint.h>

#define DM   1024
#define NH   16
#define HD   64
#define BB   4
#define TT   2048
#define MT   (BB * TT)        // 8192 rows

// Scratch (allocation rules: __device__ globals only)
__device__ float g_Q[(size_t)MT * DM];
__device__ float g_K[(size_t)MT * DM];
__device__ float g_V[(size_t)MT * DM];
__device__ float g_C[(size_t)MT * DM];

// ---------------------------------------------------------------------------
// tf32 helpers (sm_80-era mma.sync — compute_103-safe, no tcgen05)
// ---------------------------------------------------------------------------
__device__ __forceinline__ uint32_t f2tf32(float x) {
    uint32_t r;
    asm("cvt.rna.tf32.f32 %0, %1;" : "=r"(r) : "f"(x));
    return r;
}

// D(16x8,f32) += A(16x8,tf32,row) * B(8x8,tf32,col)
__device__ __forceinline__ void mma_tf32(float4& d,
                                         uint32_t a0, uint32_t a1, uint32_t a2, uint32_t a3,
                                         uint32_t b0, uint32_t b1) {
    asm volatile(
        "mma.sync.aligned.m16n8k8.row.col.f32.tf32.tf32.f32 "
        "{%0,%1,%2,%3}, {%4,%5,%6,%7}, {%8,%9}, {%0,%1,%2,%3};"
        : "+f"(d.x), "+f"(d.y), "+f"(d.z), "+f"(d.w)
        : "r"(a0), "r"(a1), "r"(a2), "r"(a3), "r"(b0), "r"(b1));
}

// ---------------------------------------------------------------------------
// tf32 tensor-core GEMM: C[m][n] = sum_k A[m][k] * W[n][k] + bias[n]
// (A: MxK row-major, W: NxK row-major — torch Linear y = A @ W^T + b)
// CTA tile 128x128, BK=32, 256 threads = 8 warps, warp tile 64x32.
// Smem stride 36 floats -> conflict-free 32-bit fragment loads.
// MODE 0: out[m*DM+n] (B,T,D). MODE 1: head-split (B,H,T,hd).
// ---------------------------------------------------------------------------
#define SST 36   // smem row stride in floats

template <int MODE>
__global__ __launch_bounds__(256, 2) void gemm_mma(
    const float* __restrict__ A, const float* __restrict__ W,
    const float* __restrict__ bias, float* __restrict__ out)
{
    __shared__ float As[128 * SST];
    __shared__ float Ws[128 * SST];

    const int tid  = threadIdx.x;
    const int lane = tid & 31;
    const int wid  = tid >> 5;
    const int wm   = (wid & 1) * 64;   // warp M offset within CTA tile
    const int wn   = (wid >> 1) * 32;  // warp N offset
    const int bm   = blockIdx.y * 128;
    const int bn   = blockIdx.x * 128;

    const int lrow4 = lane >> 2;   // 0..7
    const int lcol4 = lane & 3;    // 0..3

    float4 acc[4][4];
#pragma unroll
    for (int i = 0; i < 4; i++)
#pragma unroll
        for (int j = 0; j < 4; j++) acc[i][j] = make_float4(0.f, 0.f, 0.f, 0.f);

    for (int k0 = 0; k0 < DM; k0 += 32) {
        // Prefetch A/W chunk (128 rows x 32 k) to registers
        float4 va[4], vb[4];
#pragma unroll
        for (int i = 0; i < 4; i++) {
            const int idx = tid + i * 256;      // 0..1023
            const int row = idx >> 3;           // 0..127
            const int c4  = idx & 7;            // 0..7
            va[i] = *(const float4*)(A + (size_t)(bm + row) * DM + k0 + c4 * 4);
            vb[i] = *(const float4*)(W + (size_t)(bn + row) * DM + k0 + c4 * 4);
        }
        __syncthreads();   // previous iteration's compute done reading smem
#pragma unroll
        for (int i = 0; i < 4; i++) {
            const int idx = tid + i * 256;
            const int row = idx >> 3;
            const int c4  = idx & 7;
            float4 ta, tb;
            ta.x = __uint_as_float(f2tf32(va[i].x));
            ta.y = __uint_as_float(f2tf32(va[i].y));
            ta.z = __uint_as_float(f2tf32(va[i].z));
            ta.w = __uint_as_float(f2tf32(va[i].w));
            tb.x = __uint_as_float(f2tf32(vb[i].x));
            tb.y = __uint_as_float(f2tf32(vb[i].y));
            tb.z = __uint_as_float(f2tf32(vb[i].z));
            tb.w = __uint_as_float(f2tf32(vb[i].w));
            *(float4*)&As[row * SST + c4 * 4] = ta;
            *(float4*)&Ws[row * SST + c4 * 4] = tb;
        }
        __syncthreads();

#pragma unroll
        for (int ks = 0; ks < 4; ks++) {
            const int kk = ks * 8;
            uint32_t af[4][4], bf[4][2];
#pragma unroll
            for (int mt = 0; mt < 4; mt++) {
                const int r = wm + mt * 16 + lrow4;
                af[mt][0] = __float_as_uint(As[(r    ) * SST + kk     + lcol4]);
                af[mt][1] = __float_as_uint(As[(r + 8) * SST + kk     + lcol4]);
                af[mt][2] = __float_as_uint(As[(r    ) * SST + kk + 4 + lcol4]);
                af[mt][3] = __float_as_uint(As[(r + 8) * SST + kk + 4 + lcol4]);
            }
#pragma unroll
            for (int nt = 0; nt < 4; nt++) {
                const int c = wn + nt * 8 + lrow4;
                bf[nt][0] = __float_as_uint(Ws[c * SST + kk     + lcol4]);
                bf[nt][1] = __float_as_uint(Ws[c * SST + kk + 4 + lcol4]);
            }
#pragma unroll
            for (int mt = 0; mt < 4; mt++)
#pragma unroll
                for (int nt = 0; nt < 4; nt++)
                    mma_tf32(acc[mt][nt],
                             af[mt][0], af[mt][1], af[mt][2], af[mt][3],
                             bf[nt][0], bf[nt][1]);
        }
    }

    // Epilogue: c.x,c.y at (row, col..col+1); c.z,c.w at (row+8, ...)
#pragma unroll
    for (int mt = 0; mt < 4; mt++) {
        const int m0 = bm + wm + mt * 16 + lrow4;
#pragma unroll
        for (int nt = 0; nt < 4; nt++) {
            const int n0 = bn + wn + nt * 8 + lcol4 * 2;
            const float b0 = __ldg(bias + n0);
            const float b1 = __ldg(bias + n0 + 1);
            float2 v0 = make_float2(acc[mt][nt].x + b0, acc[mt][nt].y + b1);
            float2 v1 = make_float2(acc[mt][nt].z + b0, acc[mt][nt].w + b1);
            if (MODE == 0) {
                *(float2*)(out + (size_t)m0 * DM + n0)       = v0;
                *(float2*)(out + (size_t)(m0 + 8) * DM + n0) = v1;
            } else {
                const int h = n0 >> 6;
                const int d = n0 & 63;
                const int b_0 = m0 / TT,       t0 = m0 % TT;
                const int b_1 = (m0 + 8) / TT, t1 = (m0 + 8) % TT;
                *(float2*)(out + ((size_t)(b_0 * NH + h) * TT + t0) * HD + d) = v0;
                *(float2*)(out + ((size_t)(b_1 * NH + h) * TT + t1) * HD + d) = v1;
            }
        }
    }
}

// ---------------------------------------------------------------------------
// Causal flash attention, fp32 SIMT with GEMM-style register micro-tiles.
// BQ=128 queries x BK=64 keys per iteration, 256 threads.
// Thread (ty,tx): ty=tid/16 owns 8 q-rows, tx=tid%16 owns 4 cols.
// Q,K stored d-major (transposed) in smem so operand fetches are LDS.128.
// ---------------------------------------------------------------------------
#define QS_STRIDE 132
#define KS_STRIDE 68
#define QS_OFF 0
#define KS_OFF (64 * QS_STRIDE)             // 8448
#define VS_OFF (KS_OFF + 64 * KS_STRIDE)    // 12800
#define PS_OFF (VS_OFF + 64 * KS_STRIDE)    // 17152
#define ATT_SMEM ((PS_OFF + 128 * KS_STRIDE) * (int)sizeof(float))  // 103424 B

__global__ __launch_bounds__(256) void attn_kernel()
{
    extern __shared__ float sm[];
    const int tid = threadIdx.x;
    const int ty = tid >> 4;        // 0..15 -> q rows [ty*8, ty*8+8)
    const int tx = tid & 15;        // 0..15 -> cols  [tx*4, tx*4+4)

    const int qt = blockIdx.x;      // 0..15
    const int h  = blockIdx.y;
    const int b  = blockIdx.z;
    const size_t base = (size_t)(b * NH + h) * TT * HD;
    const int q0 = qt * 128;

    // Load Q tile transposed: Qs[d][q]
#pragma unroll
    for (int i = 0; i < 8; i++) {
        const int idx = tid + i * 256;     // 0..2047
        const int q   = idx >> 4;          // 0..127
        const int c4  = idx & 15;          // d group
        float4 v = *(const float4*)(g_Q + base + (size_t)(q0 + q) * HD + c4 * 4);
        sm[QS_OFF + (c4 * 4 + 0) * QS_STRIDE + q] = v.x;
        sm[QS_OFF + (c4 * 4 + 1) * QS_STRIDE + q] = v.y;
        sm[QS_OFF + (c4 * 4 + 2) * QS_STRIDE + q] = v.z;
        sm[QS_OFF + (c4 * 4 + 3) * QS_STRIDE + q] = v.w;
    }

    float m_i[8], l_i[8], acc[8][4];
#pragma unroll
    for (int r = 0; r < 8; r++) {
        m_i[r] = -1e30f; l_i[r] = 0.f;
#pragma unroll
        for (int i = 0; i < 4; i++) acc[r][i] = 0.f;
    }

    const int ntiles = 2 * qt + 2;
    for (int j = 0; j < ntiles; j++) {
        // Prefetch K (to transpose) and V
        float4 kr[4], vr[4];
#pragma unroll
        for (int i = 0; i < 4; i++) {
            const int idx = tid + i * 256;   // 0..1023
            const int r   = idx >> 4;        // 0..63
            const int c4  = idx & 15;
            kr[i] = *(const float4*)(g_K + base + (size_t)(j * 64 + r) * HD + c4 * 4);
            vr[i] = *(const float4*)(g_V + base + (size_t)(j * 64 + r) * HD + c4 * 4);
        }
        __syncthreads();   // previous PV done reading Vs/Ps
#pragma unroll
        for (int i = 0; i < 4; i++) {
            const int idx = tid + i * 256;
            const int r   = idx >> 4;
            const int c4  = idx & 15;
            sm[KS_OFF + (c4 * 4 + 0) * KS_STRIDE + r] = kr[i].x;
            sm[KS_OFF + (c4 * 4 + 1) * KS_STRIDE + r] = kr[i].y;
            sm[KS_OFF + (c4 * 4 + 2) * KS_STRIDE + r] = kr[i].z;
            sm[KS_OFF + (c4 * 4 + 3) * KS_STRIDE + r] = kr[i].w;
            *(float4*)&sm[VS_OFF + r * KS_STRIDE + c4 * 4] = vr[i];
        }
        __syncthreads();

        // S = Q @ K^T  (8x4 micro-tile)
        float s[8][4];
#pragma unroll
        for (int r = 0; r < 8; r++)
#pragma unroll
            for (int i = 0; i < 4; i++) s[r][i] = 0.f;

#pragma unroll 16
        for (int d = 0; d < 64; d++) {
            float a[8], bb[4];
            *(float4*)(a)     = *(const float4*)&sm[QS_OFF + d * QS_STRIDE + ty * 8];
            *(float4*)(a + 4) = *(const float4*)&sm[QS_OFF + d * QS_STRIDE + ty * 8 + 4];
            *(float4*)(bb)    = *(const float4*)&sm[KS_OFF + d * KS_STRIDE + tx * 4];
#pragma unroll
            for (int r = 0; r < 8; r++)
#pragma unroll
                for (int i = 0; i < 4; i++)
                    s[r][i] = fmaf(a[r], bb[i], s[r][i]);
        }

        // Scale + causal mask (only the last two key tiles can be masked)
        const bool need_mask = (j >= 2 * qt);
#pragma unroll
        for (int r = 0; r < 8; r++) {
            const int qrow = q0 + ty * 8 + r;
#pragma unroll
            for (int i = 0; i < 4; i++) {
                s[r][i] *= 0.125f;
                if (need_mask && (j * 64 + tx * 4 + i > qrow)) s[r][i] = -1e30f;
            }
        }

        // Online softmax per row (reduce across the 16-lane tx group)
#pragma unroll
        for (int r = 0; r < 8; r++) {
            float mloc = fmaxf(fmaxf(s[r][0], s[r][1]), fmaxf(s[r][2], s[r][3]));
            mloc = fmaxf(mloc, __shfl_xor_sync(0xffffffffu, mloc, 1));
            mloc = fmaxf(mloc, __shfl_xor_sync(0xffffffffu, mloc, 2));
            mloc = fmaxf(mloc, __shfl_xor_sync(0xffffffffu, mloc, 4));
            mloc = fmaxf(mloc, __shfl_xor_sync(0xffffffffu, mloc, 8));
            const float mn = fmaxf(m_i[r], mloc);

            float ps = 0.f;
#pragma unroll
            for (int i = 0; i < 4; i++) {
                s[r][i] = __expf(s[r][i] - mn);
                ps += s[r][i];
            }
            ps += __shfl_xor_sync(0xffffffffu, ps, 1);
            ps += __shfl_xor_sync(0xffffffffu, ps, 2);
            ps += __shfl_xor_sync(0xffffffffu, ps, 4);
            ps += __shfl_xor_sync(0xffffffffu, ps, 8);

            const float corr = __expf(m_i[r] - mn);
            l_i[r] = l_i[r] * corr + ps;
            m_i[r] = mn;
#pragma unroll
            for (int i = 0; i < 4; i++) acc[r][i] *= corr;

            // Stage P to smem: Ps[row][k]
            *(float4*)&sm[PS_OFF + (ty * 8 + r) * KS_STRIDE + tx * 4] = *(float4*)s[r];
        }
        __syncthreads();   // P visible

        // O += P @ V  (k in steps of 4)
#pragma unroll 4
        for (int k4 = 0; k4 < 16; k4++) {
            float p[8][4], v[4][4];
#pragma unroll
            for (int r = 0; r < 8; r++)
                *(float4*)p[r] = *(const float4*)&sm[PS_OFF + (ty * 8 + r) * KS_STRIDE + k4 * 4];
#pragma unroll
            for (int u = 0; u < 4; u++)
                *(float4*)v[u] = *(const float4*)&sm[VS_OFF + (k4 * 4 + u) * KS_STRIDE + tx * 4];
#pragma unroll
            for (int u = 0; u < 4; u++)
#pragma unroll
                for (int r = 0; r < 8; r++)
#pragma unroll
                    for (int i = 0; i < 4; i++)
                        acc[r][i] = fmaf(p[r][u], v[u][i], acc[r][i]);
        }
    }

    // Normalize + write ctx in (B,T,D) layout
#pragma unroll
    for (int r = 0; r < 8; r++) {
        const float inv = 1.f / l_i[r];
        float4 o = make_float4(acc[r][0] * inv, acc[r][1] * inv,
                               acc[r][2] * inv, acc[r][3] * inv);
        *(float4*)(g_C + ((size_t)(b * TT + q0 + ty * 8 + r)) * DM + h * HD + tx * 4) = o;
    }
}

// ---------------------------------------------------------------------------
extern "C" void kernel_launch(void* const* d_in, const int* in_sizes, int n_in,
                              void* d_out, int out_size)
{
    const float* x  = (const float*)d_in[0];
    const float* Wq = (const float*)d_in[1];
    const float* bq = (const float*)d_in[2];
    const float* Wk = (const float*)d_in[3];
    const float* bk = (const float*)d_in[4];
    const float* Wv = (const float*)d_in[5];
    const float* bv = (const float*)d_in[6];
    const float* Wo = (const float*)d_in[7];
    const float* bo = (const float*)d_in[8];
    float* out = (float*)d_out;

    float *Qp, *Kp, *Vp, *Cp;
    cudaGetSymbolAddress((void**)&Qp, g_Q);
    cudaGetSymbolAddress((void**)&Kp, g_K);
    cudaGetSymbolAddress((void**)&Vp, g_V);
    cudaGetSymbolAddress((void**)&Cp, g_C);

    cudaFuncSetAttribute(attn_kernel,
                         cudaFuncAttributeMaxDynamicSharedMemorySize, ATT_SMEM);

    dim3 ggrid(DM / 128, MT / 128);   // (8, 64)
    gemm_mma<1><<<ggrid, 256>>>(x, Wq, bq, Qp);
    gemm_mma<1><<<ggrid, 256>>>(x, Wk, bk, Kp);
    gemm_mma<1><<<ggrid, 256>>>(x, Wv, bv, Vp);

    dim3 agrid(TT / 128, NH, BB);     // (16, 16, 4)
    attn_kernel<<<agrid, 256, ATT_SMEM>>>();

    gemm_mma<0><<<ggrid, 256>>>(Cp, Wo, bo, out);
}